// round 1
// baseline (speedup 1.0000x reference)
#include <cuda_runtime.h>
#include <math.h>

// SO3_Rotation: out[e] = blockdiag(D^0..D^4)(R_e) @ embedding[e]
// D^l computed in closed form (no expm):
//   D^l = A(alpha) * B(beta) * A(gamma)
//   A(theta): sparse cos/sin matrix (exact exp of the "y" generator in e3nn real basis)
//   B(beta):  parity-block matrix built from Wigner little-d d^l(beta)

#define NROWS 25       // (LMAX+1)^2
#define NCH   64
#define ETILE 1600     // NROWS*NCH
#define NDTOT 165      // 1+9+25+49+81

__constant__ float c_fact[9] = {1.f,1.f,2.f,6.f,24.f,120.f,720.f,5040.f,40320.f};
__constant__ int   c_off[6]  = {0,1,10,35,84,165};

__device__ __forceinline__ float powi(float x, int e) {
    float r = 1.f;
    for (int i = 0; i < e; i++) r *= x;
    return r;
}

// Standard Wigner little-d, convention <m'| e^{-i beta Jy} |m>, via half-angles ch=cos(b/2), sh=sin(b/2)
__device__ float wig_d(int l, int mp, int m, float ch, float sh) {
    float pref = sqrtf(c_fact[l+mp]*c_fact[l-mp]*c_fact[l+m]*c_fact[l-m]);
    int k0 = (m - mp > 0) ? (m - mp) : 0;
    int k1 = (l + m < l - mp) ? (l + m) : (l - mp);
    float sum = 0.f;
    for (int k = k0; k <= k1; k++) {
        float denom = c_fact[l+m-k]*c_fact[k]*c_fact[mp-m+k]*c_fact[l-mp-k];
        float t = powi(ch, 2*l + m - mp - 2*k) * powi(sh, mp - m + 2*k) / denom;
        sum += ((mp - m + k) & 1) ? -t : t;
    }
    return pref * sum;
}

// trig smem layout
#define CA 0
#define SA 5
#define CG 10
#define SG 15
#define CH 20
#define SH 21

__global__ void __launch_bounds__(256, 8)
so3_rot_kernel(const float* __restrict__ rot,
               const float* __restrict__ emb,
               float* __restrict__ out,
               int E)
{
    __shared__ float sEmb[ETILE];
    __shared__ float sB[NDTOT];
    __shared__ float sD[NDTOT];
    __shared__ float sTrig[22];

    const int e = blockIdx.x;
    if (e >= E) return;
    const int tid = threadIdx.x;

    // ---- thread 0: Euler trig (exactly matching reference extraction) ----
    if (tid == 0) {
        const float* R = rot + (size_t)e * 9;
        float x0 = R[0*3+1], x1 = R[1*3+1], x2 = R[2*3+1];
        float inv = rsqrtf(x0*x0 + x1*x1 + x2*x2);
        x0 *= inv; x1 *= inv; x2 *= inv;
        x0 = fminf(1.f, fmaxf(-1.f, x0));
        x1 = fminf(1.f, fmaxf(-1.f, x1));
        x2 = fminf(1.f, fmaxf(-1.f, x2));
        float cb = x1;                       // cos(beta), beta in [0,pi]
        float r  = sqrtf(x0*x0 + x2*x2);
        float ca, sa;
        if (r > 1e-20f) { ca = x2 / r; sa = x0 / r; } else { ca = 1.f; sa = 0.f; }
        // gamma from R' = (rot_y(a) rot_x(b))^T R ; row 0 of Rab^T = (ca, 0, -sa)
        float gy = ca * R[0*3+2] - sa * R[2*3+2];
        float gx = ca * R[0*3+0] - sa * R[2*3+0];
        float gr = sqrtf(gx*gx + gy*gy);
        float cg, sg;
        if (gr > 1e-20f) { cg = gx / gr; sg = gy / gr; } else { cg = 1.f; sg = 0.f; }
        // half angles of beta
        sTrig[CH] = sqrtf(fmaxf(0.f, 0.5f * (1.f + cb)));
        sTrig[SH] = sqrtf(fmaxf(0.f, 0.5f * (1.f - cb)));
        // Chebyshev multiples of alpha / gamma
        float cka = 1.f, ska = 0.f, ckg = 1.f, skg = 0.f;
        sTrig[CA+0] = 1.f; sTrig[SA+0] = 0.f;
        sTrig[CG+0] = 1.f; sTrig[SG+0] = 0.f;
        for (int k = 1; k <= 4; k++) {
            float nca = cka*ca - ska*sa, nsa = ska*ca + cka*sa;
            cka = nca; ska = nsa;
            sTrig[CA+k] = cka; sTrig[SA+k] = ska;
            float ncg = ckg*cg - skg*sg, nsg = skg*cg + ckg*sg;
            ckg = ncg; skg = nsg;
            sTrig[CG+k] = ckg; sTrig[SG+k] = skg;
        }
    }

    // ---- stage embedding tile (coalesced) ----
    {
        const float* ep = emb + (size_t)e * ETILE;
        #pragma unroll
        for (int k = 0; k < ETILE / 256; k++)
            sEmb[tid + k * 256] = ep[tid + k * 256];
        // ETILE = 1600 = 6*256 + 64
        if (tid < ETILE - (ETILE / 256) * 256)
            sEmb[(ETILE / 256) * 256 + tid] = ep[(ETILE / 256) * 256 + tid];
    }
    __syncthreads();

    // ---- B(beta) = exp(beta * X0), via little-d + real-basis transform ----
    if (tid < NDTOT) {
        int t = tid;
        int l = 0;
        while (t >= c_off[l + 1]) l++;
        int loc = t - c_off[l];
        int n1 = 2 * l + 1;
        int i = loc / n1, j = loc % n1;
        int ma = i - l, nb = j - l;
        float ch = sTrig[CH], sh = sTrig[SH];
        float v;
        bool negA = (ma < 0), negB = (nb < 0);
        if (negA != negB) {
            v = 0.f;                                   // parity blocks don't mix
        } else if (negA) {
            int p = -ma, q = -nb;
            float d1 = wig_d(l, p,  q, ch, sh);
            float d2 = wig_d(l, p, -q, ch, sh);
            float s1 = ((p + q) & 1) ? -d1 : d1;
            float s2 = (p & 1) ? -d2 : d2;
            v = s1 - s2;
        } else if (ma > 0 && nb > 0) {
            int p = ma, q = nb;
            float d1 = wig_d(l, p,  q, ch, sh);
            float d2 = wig_d(l, p, -q, ch, sh);
            float s1 = ((p + q) & 1) ? -d1 : d1;
            float s2 = (p & 1) ? -d2 : d2;
            v = s1 + s2;
        } else if (ma == 0 && nb == 0) {
            v = wig_d(l, 0, 0, ch, sh);
        } else if (ma == 0) {
            int q = nb;
            float d = wig_d(l, 0, q, ch, sh);
            v = 1.41421356237f * ((q & 1) ? -d : d);
        } else {
            int p = ma;
            float d = wig_d(l, p, 0, ch, sh);
            v = 1.41421356237f * ((p & 1) ? -d : d);
        }
        sB[tid] = v;
    }
    __syncthreads();

    // ---- D = A(alpha) * B * A(gamma), using sparsity of A (<=2 nonzeros/row/col) ----
    if (tid < NDTOT) {
        int t = tid;
        int l = 0;
        while (t >= c_off[l + 1]) l++;
        int loc = t - c_off[l];
        int n1 = 2 * l + 1;
        int i = loc / n1, j = loc % n1;
        int ma = i - l, nb = j - l;
        int p = ma < 0 ? -ma : ma;
        int q = nb < 0 ? -nb : nb;
        float rc = sTrig[CA + p];                                 // coef for column l+ma of A(alpha)
        float rs = (ma > 0) ? -sTrig[SA + p] : sTrig[SA + p];     // coef for column l-ma
        float cc = sTrig[CG + q];                                 // coef for row l+nb of A(gamma)
        float cs = (nb > 0) ? sTrig[SG + q] : -sTrig[SG + q];     // coef for row l-nb
        const float* Bl = sB + c_off[l];
        float acc = rc * cc * Bl[(l + ma) * n1 + (l + nb)];
        if (nb != 0) acc += rc * cs * Bl[(l + ma) * n1 + (l - nb)];
        if (ma != 0) {
            acc += rs * cc * Bl[(l - ma) * n1 + (l + nb)];
            if (nb != 0) acc += rs * cs * Bl[(l - ma) * n1 + (l - nb)];
        }
        sD[tid] = acc;
    }
    __syncthreads();

    // ---- apply: out[i,c] = sum_j D^l[i-b0, j] * emb[b0+j, c] ----
    {
        const int c  = tid & 63;
        const int r0 = tid >> 6;      // 0..3
        float* op = out + (size_t)e * ETILE;
        for (int i = r0; i < NROWS; i += 4) {
            int l = (i == 0) ? 0 : (i < 4 ? 1 : (i < 9 ? 2 : (i < 16 ? 3 : 4)));
            int b0 = l * l;
            int n1 = 2 * l + 1;
            const float* Drow = sD + c_off[l] + (i - b0) * n1;
            float acc = 0.f;
            for (int j = 0; j < n1; j++)
                acc = fmaf(Drow[j], sEmb[(b0 + j) * NCH + c], acc);
            op[i * NCH + c] = acc;
        }
    }
}

extern "C" void kernel_launch(void* const* d_in, const int* in_sizes, int n_in,
                              void* d_out, int out_size)
{
    const float* rot = (const float*)d_in[0];   // (E,3,3)
    const float* emb = (const float*)d_in[1];   // (E,25,64)
    float* out = (float*)d_out;                 // (E,25,64)
    int E = in_sizes[0] / 9;
    so3_rot_kernel<<<E, 256>>>(rot, emb, out, E);
}

// round 2
// speedup vs baseline: 3.7474x; 3.7474x over previous
#include <cuda_runtime.h>
#include <math.h>

// SO3_Rotation split into two kernels:
//  A) so3_dgen : one thread per element builds the 165 Wigner-D entries in
//     closed form (template-unrolled, all coefficients compile-time constants)
//     and writes them transposed g_D[k*E+e] (coalesced; L2-resident, 33MB).
//  B) so3_apply: block per element, block-diagonal matmul with fully
//     constant-indexed unrolled loops (no dynamic register indexing).

#define NROWS 25
#define NCH   64
#define ETILE 1600
#define NDTOT 165
#define EMAX  50048

__device__ float g_D[(size_t)NDTOT * EMAX];

// ---------------- compile-time helpers ----------------
__host__ __device__ constexpr double cfact(int n){ double r=1.0; for(int i=2;i<=n;++i) r*=(double)i; return r; }
__host__ __device__ constexpr double csqrt_(double x){ double r = (x>1.0)?x:1.0; for(int i=0;i<100;++i) r = 0.5*(r + x/r); return r; }
__host__ __device__ constexpr int cmax(int a,int b){ return a>b?a:b; }
__host__ __device__ constexpr int cmin(int a,int b){ return a<b?a:b; }
__host__ __device__ constexpr bool nzB(int x,int y){
    return (x>0&&y>0)||(x<0&&y<0)||(x==0&&y>=0)||(x>0&&y==0);
}

// Wigner little-d term sum: d^L_{P,Q}(beta) via half-angle powers.
template<int L,int P,int Q,int K,bool Done>
struct DTerm {
    static constexpr float coef = (float)(
        ((((P-Q+K)&1)? -1.0 : 1.0) *
         csqrt_(cfact(L+P)*cfact(L-P)*cfact(L+Q)*cfact(L-Q)) /
         (cfact(L+Q-K)*cfact(K)*cfact(P-Q+K)*cfact(L-P-K))));
    __device__ static __forceinline__ float eval(const float* chp, const float* shp){
        constexpr int K1 = cmin(L+Q, L-P);
        return fmaf(coef, chp[2*L+Q-P-2*K]*shp[P-Q+2*K],
                    DTerm<L,P,Q,K+1,(K+1>K1)>::eval(chp,shp));
    }
};
template<int L,int P,int Q,int K>
struct DTerm<L,P,Q,K,true> {
    __device__ static __forceinline__ float eval(const float*, const float*){ return 0.f; }
};

template<int L,int P,int Q>
__device__ __forceinline__ float dval(const float* chp, const float* shp){
    constexpr int K0 = cmax(0, Q-P);
    constexpr int K1 = cmin(L+Q, L-P);
    return DTerm<L,P,Q,K0,(K0>K1)>::eval(chp,shp);
}

// B(beta) entry in the e3nn real basis (parity-block structure).
template<int L,int X,int Y>
__device__ __forceinline__ float Bval(const float* chp, const float* shp){
    if constexpr (X>0 && Y>0){
        constexpr float s1 = ((X+Y)&1)? -1.f : 1.f;
        constexpr float s2 = (X&1)? -1.f : 1.f;
        return s1*dval<L,X,Y>(chp,shp) + s2*dval<L,X,-Y>(chp,shp);
    } else if constexpr (X<0 && Y<0){
        constexpr int P=-X, Q=-Y;
        constexpr float s1 = ((P+Q)&1)? -1.f : 1.f;
        constexpr float s2 = (P&1)? -1.f : 1.f;
        return s1*dval<L,P,Q>(chp,shp) - s2*dval<L,P,-Q>(chp,shp);
    } else if constexpr (X==0 && Y==0){
        return dval<L,0,0>(chp,shp);
    } else if constexpr (X==0 && Y>0){
        constexpr float s = ((Y&1)? -1.f : 1.f) * 1.41421356237309515f;
        return s*dval<L,0,Y>(chp,shp);
    } else if constexpr (X>0 && Y==0){
        constexpr float s = ((X&1)? -1.f : 1.f) * 1.41421356237309515f;
        return s*dval<L,X,0>(chp,shp);
    } else {
        return 0.f;
    }
}

struct Trig { float cat[5], sat[5], cgt[5], sgt[5]; };

// D = A(alpha) * B(beta) * A(gamma): each entry combines at most 4 B-values,
// of which only the parity-matching ones are nonzero (compile-time pruned).
template<int L,int OFF,int IJ,bool Done>
struct DLoop {
    __device__ static __forceinline__ void run(float* __restrict__ base, size_t sE,
            const float* chp, const float* shp, const Trig& T){
        constexpr int N1 = 2*L+1;
        constexpr int I = IJ / N1, J = IJ % N1;
        constexpr int MA = I - L, NB = J - L;
        constexpr int P = MA<0 ? -MA : MA;
        constexpr int Q = NB<0 ? -NB : NB;
        float rc = T.cat[P];
        float rs = (MA>0) ? -T.sat[P] : T.sat[P];
        float cc = T.cgt[Q];
        float cs = (NB>0) ? T.sgt[Q] : -T.sgt[Q];
        float acc = 0.f;
        if constexpr (nzB(MA,NB))
            acc = fmaf(rc*cc, Bval<L,MA,NB>(chp,shp), acc);
        if constexpr (NB!=0){ if constexpr (nzB(MA,-NB))
            acc = fmaf(rc*cs, Bval<L,MA,(NB!=0)?-NB:0>(chp,shp), acc); }
        if constexpr (MA!=0){ if constexpr (nzB(-MA,NB))
            acc = fmaf(rs*cc, Bval<L,(MA!=0)?-MA:0,NB>(chp,shp), acc); }
        if constexpr (MA!=0 && NB!=0){ if constexpr (nzB(-MA,-NB))
            acc = fmaf(rs*cs, Bval<L,(MA!=0)?-MA:0,(NB!=0)?-NB:0>(chp,shp), acc); }
        base[(size_t)(OFF+IJ)*sE] = acc;
        DLoop<L,OFF,IJ+1,(IJ+1==N1*N1)>::run(base, sE, chp, shp, T);
    }
};
template<int L,int OFF,int IJ>
struct DLoop<L,OFF,IJ,true>{
    __device__ static __forceinline__ void run(float*, size_t, const float*, const float*, const Trig&){}
};

// ---------------- kernel A: build D ----------------
__global__ void __launch_bounds__(256)
so3_dgen(const float* __restrict__ rot, int E)
{
    int e = blockIdx.x * 256 + threadIdx.x;
    if (e >= E) return;
    const float* R = rot + (size_t)e * 9;
    float r00=R[0], r01=R[1], r02=R[2];
    float r10=R[3], r11=R[4], r12=R[5];
    float r20=R[6], r21=R[7], r22=R[8];
    (void)r10; (void)r12;

    // Euler extraction matching the reference exactly
    float x0=r01, x1=r11, x2=r21;
    float inv = rsqrtf(x0*x0 + x1*x1 + x2*x2);
    x0*=inv; x1*=inv; x2*=inv;
    x0 = fminf(1.f, fmaxf(-1.f, x0));
    x1 = fminf(1.f, fmaxf(-1.f, x1));
    x2 = fminf(1.f, fmaxf(-1.f, x2));
    float cb = x1;
    float rxz = sqrtf(x0*x0 + x2*x2);
    float ca, sa;
    if (rxz > 1e-20f){ ca = x2/rxz; sa = x0/rxz; } else { ca = 1.f; sa = 0.f; }
    float gy = ca*r02 - sa*r22;
    float gx = ca*r00 - sa*r20;
    float gr = sqrtf(gx*gx + gy*gy);
    float cg, sg;
    if (gr > 1e-20f){ cg = gx/gr; sg = gy/gr; } else { cg = 1.f; sg = 0.f; }

    // half-angle powers of beta
    float ch = sqrtf(fmaxf(0.f, 0.5f*(1.f+cb)));
    float sh = sqrtf(fmaxf(0.f, 0.5f*(1.f-cb)));
    float chp[9], shp[9];
    chp[0]=1.f; shp[0]=1.f;
    #pragma unroll
    for (int k=1;k<9;k++){ chp[k]=chp[k-1]*ch; shp[k]=shp[k-1]*sh; }

    // Chebyshev multiples of alpha / gamma
    Trig T;
    T.cat[0]=1.f; T.sat[0]=0.f; T.cgt[0]=1.f; T.sgt[0]=0.f;
    #pragma unroll
    for (int k=1;k<5;k++){
        float c0=T.cat[k-1], s0=T.sat[k-1];
        T.cat[k]=c0*ca - s0*sa;  T.sat[k]=s0*ca + c0*sa;
        float c1=T.cgt[k-1], s1=T.sgt[k-1];
        T.cgt[k]=c1*cg - s1*sg;  T.sgt[k]=s1*cg + c1*sg;
    }

    float* base = g_D + e;
    size_t sE = (size_t)E;
    DLoop<0,  0, 0, false>::run(base, sE, chp, shp, T);
    DLoop<1,  1, 0, false>::run(base, sE, chp, shp, T);
    DLoop<2, 10, 0, false>::run(base, sE, chp, shp, T);
    DLoop<3, 35, 0, false>::run(base, sE, chp, shp, T);
    DLoop<4, 84, 0, false>::run(base, sE, chp, shp, T);
}

// ---------------- kernel B: apply block-diagonal D ----------------
__host__ __device__ constexpr int rb0(int i){ return i==0?0 : (i<4?1 : (i<9?4 : (i<16?9 : 16))); }
__host__ __device__ constexpr int rn1(int i){ return i==0?1 : (i<4?3 : (i<9?5 : (i<16?7 : 9))); }
__host__ __device__ constexpr int rdoff(int i){
    int b0 = rb0(i), n1 = rn1(i);
    int off = (i==0)?0 : (i<4?1 : (i<9?10 : (i<16?35 : 84)));
    return off + (i-b0)*n1;
}

template<int R>
__device__ __forceinline__ void doRows(const float* __restrict__ sD,
                                       const float* eR,
                                       float* __restrict__ op, int c)
{
    #pragma unroll
    for (int i=R; i<25; i+=4){
        const int b0 = rb0(i), n1 = rn1(i), dof = rdoff(i);
        float acc = 0.f;
        #pragma unroll
        for (int j=0;j<n1;j++)
            acc = fmaf(sD[dof+j], eR[b0+j], acc);
        op[i*NCH + c] = acc;
    }
}

__global__ void __launch_bounds__(256, 8)
so3_apply(const float* __restrict__ emb, float* __restrict__ out, int E)
{
    __shared__ float sEmb[ETILE];
    __shared__ float sD[NDTOT];
    const int e   = blockIdx.x;
    const int tid = threadIdx.x;

    if (tid < NDTOT) sD[tid] = g_D[(size_t)tid * E + e];

    const float4* ep  = (const float4*)(emb + (size_t)e * ETILE);
    float4*       sE4 = (float4*)sEmb;
    sE4[tid] = ep[tid];                       // 256 of 400
    if (tid < 144) sE4[256 + tid] = ep[256 + tid];
    __syncthreads();

    const int lane  = tid & 31;
    const int w     = tid >> 5;
    const int c     = lane + ((w & 1) << 5);  // 0..63
    const int rslot = w >> 1;                 // 0..3, uniform per warp

    float eR[25];
    #pragma unroll
    for (int j=0;j<25;j++) eR[j] = sEmb[j*NCH + c];

    float* op = out + (size_t)e * ETILE;
    switch (rslot){
        case 0: doRows<0>(sD, eR, op, c); break;
        case 1: doRows<1>(sD, eR, op, c); break;
        case 2: doRows<2>(sD, eR, op, c); break;
        default: doRows<3>(sD, eR, op, c); break;
    }
}

extern "C" void kernel_launch(void* const* d_in, const int* in_sizes, int n_in,
                              void* d_out, int out_size)
{
    const float* rot = (const float*)d_in[0];   // (E,3,3)
    const float* emb = (const float*)d_in[1];   // (E,25,64)
    float* out = (float*)d_out;                 // (E,25,64)
    int E = in_sizes[0] / 9;
    so3_dgen<<<(E + 255) / 256, 256>>>(rot, E);
    so3_apply<<<E, 256>>>(emb, out, E);
}

// round 3
// speedup vs baseline: 6.0555x; 1.6159x over previous
#include <cuda_runtime.h>
#include <math.h>

// SO3_Rotation, two kernels:
//  A) so3_dgen : one thread/element builds 165 Wigner-D entries in closed form
//     (template-unrolled, compile-time coefficients), writes transposed g_D[k*E+e].
//  B) so3_apply: 16 elements per 256-thread block; each thread owns 4 channels
//     (float4) of one element and computes all 25 rows. emb goes global->reg
//     directly (no smem staging); D staged in smem, broadcast LDS.

#define NROWS 25
#define NCH   64
#define ETILE 1600
#define NDTOT 165
#define EMAX  50048
#define EPB   16          // elements per block (kernel B)
#define DPITCH 166        // padded D row in smem

__device__ float g_D[(size_t)NDTOT * EMAX];

// ---------------- compile-time helpers ----------------
__host__ __device__ constexpr double cfact(int n){ double r=1.0; for(int i=2;i<=n;++i) r*=(double)i; return r; }
__host__ __device__ constexpr double csqrt_(double x){ double r = (x>1.0)?x:1.0; for(int i=0;i<100;++i) r = 0.5*(r + x/r); return r; }
__host__ __device__ constexpr int cmax(int a,int b){ return a>b?a:b; }
__host__ __device__ constexpr int cmin(int a,int b){ return a<b?a:b; }
__host__ __device__ constexpr bool nzB(int x,int y){
    return (x>0&&y>0)||(x<0&&y<0)||(x==0&&y>=0)||(x>0&&y==0);
}

template<int L,int P,int Q,int K,bool Done>
struct DTerm {
    static constexpr float coef = (float)(
        ((((P-Q+K)&1)? -1.0 : 1.0) *
         csqrt_(cfact(L+P)*cfact(L-P)*cfact(L+Q)*cfact(L-Q)) /
         (cfact(L+Q-K)*cfact(K)*cfact(P-Q+K)*cfact(L-P-K))));
    __device__ static __forceinline__ float eval(const float* chp, const float* shp){
        constexpr int K1 = cmin(L+Q, L-P);
        return fmaf(coef, chp[2*L+Q-P-2*K]*shp[P-Q+2*K],
                    DTerm<L,P,Q,K+1,(K+1>K1)>::eval(chp,shp));
    }
};
template<int L,int P,int Q,int K>
struct DTerm<L,P,Q,K,true> {
    __device__ static __forceinline__ float eval(const float*, const float*){ return 0.f; }
};

template<int L,int P,int Q>
__device__ __forceinline__ float dval(const float* chp, const float* shp){
    constexpr int K0 = cmax(0, Q-P);
    constexpr int K1 = cmin(L+Q, L-P);
    return DTerm<L,P,Q,K0,(K0>K1)>::eval(chp,shp);
}

template<int L,int X,int Y>
__device__ __forceinline__ float Bval(const float* chp, const float* shp){
    if constexpr (X>0 && Y>0){
        constexpr float s1 = ((X+Y)&1)? -1.f : 1.f;
        constexpr float s2 = (X&1)? -1.f : 1.f;
        return s1*dval<L,X,Y>(chp,shp) + s2*dval<L,X,-Y>(chp,shp);
    } else if constexpr (X<0 && Y<0){
        constexpr int P=-X, Q=-Y;
        constexpr float s1 = ((P+Q)&1)? -1.f : 1.f;
        constexpr float s2 = (P&1)? -1.f : 1.f;
        return s1*dval<L,P,Q>(chp,shp) - s2*dval<L,P,-Q>(chp,shp);
    } else if constexpr (X==0 && Y==0){
        return dval<L,0,0>(chp,shp);
    } else if constexpr (X==0 && Y>0){
        constexpr float s = ((Y&1)? -1.f : 1.f) * 1.41421356237309515f;
        return s*dval<L,0,Y>(chp,shp);
    } else if constexpr (X>0 && Y==0){
        constexpr float s = ((X&1)? -1.f : 1.f) * 1.41421356237309515f;
        return s*dval<L,X,0>(chp,shp);
    } else {
        return 0.f;
    }
}

struct Trig { float cat[5], sat[5], cgt[5], sgt[5]; };

template<int L,int OFF,int IJ,bool Done>
struct DLoop {
    __device__ static __forceinline__ void run(float* __restrict__ base, size_t sE,
            const float* chp, const float* shp, const Trig& T){
        constexpr int N1 = 2*L+1;
        constexpr int I = IJ / N1, J = IJ % N1;
        constexpr int MA = I - L, NB = J - L;
        constexpr int P = MA<0 ? -MA : MA;
        constexpr int Q = NB<0 ? -NB : NB;
        float rc = T.cat[P];
        float rs = (MA>0) ? -T.sat[P] : T.sat[P];
        float cc = T.cgt[Q];
        float cs = (NB>0) ? T.sgt[Q] : -T.sgt[Q];
        float acc = 0.f;
        if constexpr (nzB(MA,NB))
            acc = fmaf(rc*cc, Bval<L,MA,NB>(chp,shp), acc);
        if constexpr (NB!=0){ if constexpr (nzB(MA,-NB))
            acc = fmaf(rc*cs, Bval<L,MA,(NB!=0)?-NB:0>(chp,shp), acc); }
        if constexpr (MA!=0){ if constexpr (nzB(-MA,NB))
            acc = fmaf(rs*cc, Bval<L,(MA!=0)?-MA:0,NB>(chp,shp), acc); }
        if constexpr (MA!=0 && NB!=0){ if constexpr (nzB(-MA,-NB))
            acc = fmaf(rs*cs, Bval<L,(MA!=0)?-MA:0,(NB!=0)?-NB:0>(chp,shp), acc); }
        base[(size_t)(OFF+IJ)*sE] = acc;
        DLoop<L,OFF,IJ+1,(IJ+1==N1*N1)>::run(base, sE, chp, shp, T);
    }
};
template<int L,int OFF,int IJ>
struct DLoop<L,OFF,IJ,true>{
    __device__ static __forceinline__ void run(float*, size_t, const float*, const float*, const Trig&){}
};

// ---------------- kernel A: build D ----------------
__global__ void __launch_bounds__(256)
so3_dgen(const float* __restrict__ rot, int E)
{
    int e = blockIdx.x * 256 + threadIdx.x;
    if (e >= E) return;
    const float* R = rot + (size_t)e * 9;
    float r00=R[0], r01=R[1], r02=R[2];
    float r11=R[4];
    float r20=R[6], r21=R[7], r22=R[8];

    float x0=r01, x1=r11, x2=r21;
    float inv = rsqrtf(x0*x0 + x1*x1 + x2*x2);
    x0*=inv; x1*=inv; x2*=inv;
    x0 = fminf(1.f, fmaxf(-1.f, x0));
    x1 = fminf(1.f, fmaxf(-1.f, x1));
    x2 = fminf(1.f, fmaxf(-1.f, x2));
    float cb = x1;
    float rxz = sqrtf(x0*x0 + x2*x2);
    float ca, sa;
    if (rxz > 1e-20f){ ca = x2/rxz; sa = x0/rxz; } else { ca = 1.f; sa = 0.f; }
    float gy = ca*r02 - sa*r22;
    float gx = ca*r00 - sa*r20;
    float gr = sqrtf(gx*gx + gy*gy);
    float cg, sg;
    if (gr > 1e-20f){ cg = gx/gr; sg = gy/gr; } else { cg = 1.f; sg = 0.f; }

    float ch = sqrtf(fmaxf(0.f, 0.5f*(1.f+cb)));
    float sh = sqrtf(fmaxf(0.f, 0.5f*(1.f-cb)));
    float chp[9], shp[9];
    chp[0]=1.f; shp[0]=1.f;
    #pragma unroll
    for (int k=1;k<9;k++){ chp[k]=chp[k-1]*ch; shp[k]=shp[k-1]*sh; }

    Trig T;
    T.cat[0]=1.f; T.sat[0]=0.f; T.cgt[0]=1.f; T.sgt[0]=0.f;
    #pragma unroll
    for (int k=1;k<5;k++){
        float c0=T.cat[k-1], s0=T.sat[k-1];
        T.cat[k]=c0*ca - s0*sa;  T.sat[k]=s0*ca + c0*sa;
        float c1=T.cgt[k-1], s1=T.sgt[k-1];
        T.cgt[k]=c1*cg - s1*sg;  T.sgt[k]=s1*cg + c1*sg;
    }

    float* base = g_D + e;
    size_t sE = (size_t)E;
    DLoop<0,  0, 0, false>::run(base, sE, chp, shp, T);
    DLoop<1,  1, 0, false>::run(base, sE, chp, shp, T);
    DLoop<2, 10, 0, false>::run(base, sE, chp, shp, T);
    DLoop<3, 35, 0, false>::run(base, sE, chp, shp, T);
    DLoop<4, 84, 0, false>::run(base, sE, chp, shp, T);
}

// ---------------- kernel B: apply block-diagonal D ----------------
template<int L, int B0, int DOFF>
__device__ __forceinline__ void applyL(const float* __restrict__ sDe,
                                       const float* __restrict__ ebase,
                                       float* __restrict__ obase)
{
    constexpr int N1 = 2*L+1;
    float4 eR[N1];
    #pragma unroll
    for (int j=0;j<N1;j++)
        eR[j] = *(const float4*)(ebase + (B0+j)*NCH);
    #pragma unroll
    for (int i=0;i<N1;i++){
        float4 a;
        float d0 = sDe[DOFF + i*N1];
        a.x = d0*eR[0].x; a.y = d0*eR[0].y; a.z = d0*eR[0].z; a.w = d0*eR[0].w;
        #pragma unroll
        for (int j=1;j<N1;j++){
            float d = sDe[DOFF + i*N1 + j];
            a.x = fmaf(d, eR[j].x, a.x);
            a.y = fmaf(d, eR[j].y, a.y);
            a.z = fmaf(d, eR[j].z, a.z);
            a.w = fmaf(d, eR[j].w, a.w);
        }
        *(float4*)(obase + (B0+i)*NCH) = a;
    }
}

__global__ void __launch_bounds__(256)
so3_apply(const float* __restrict__ emb, float* __restrict__ out, int E)
{
    __shared__ float sD[EPB * DPITCH];
    const int tid = threadIdx.x;
    const int e0  = blockIdx.x * EPB;

    // stage D for 16 elements: sD[el][k] = g_D[k*E + e0+el]  (coalesced reads)
    #pragma unroll
    for (int idx = tid; idx < EPB * NDTOT; idx += 256) {
        int el = idx & (EPB - 1);
        int k  = idx >> 4;
        sD[el * DPITCH + k] = g_D[(size_t)k * E + e0 + el];
    }
    __syncthreads();

    const int el     = tid >> 4;          // 0..15
    const int lane16 = tid & 15;          // 0..15 -> channels 4*lane16..+3
    const float* sDe = sD + el * DPITCH;
    const size_t off = (size_t)(e0 + el) * ETILE + lane16 * 4;
    const float* eb  = emb + off;
    float*       ob  = out + off;

    applyL<0, 0,  0>(sDe, eb, ob);
    applyL<1, 1,  1>(sDe, eb, ob);
    applyL<2, 4, 10>(sDe, eb, ob);
    applyL<3, 9, 35>(sDe, eb, ob);
    applyL<4,16, 84>(sDe, eb, ob);
}

extern "C" void kernel_launch(void* const* d_in, const int* in_sizes, int n_in,
                              void* d_out, int out_size)
{
    const float* rot = (const float*)d_in[0];   // (E,3,3)
    const float* emb = (const float*)d_in[1];   // (E,25,64)
    float* out = (float*)d_out;                 // (E,25,64)
    int E = in_sizes[0] / 9;
    so3_dgen<<<(E + 255) / 256, 256>>>(rot, E);
    so3_apply<<<(E + EPB - 1) / EPB, 256>>>(emb, out, E);
}